// round 10
// baseline (speedup 1.0000x reference)
#include <cuda_runtime.h>
#include <cuda_fp16.h>

#define NN 100000
#define EE 1600000
#define IC 128
#define HH 64

typedef unsigned long long ull;

// packed f32x2 helpers (sm_100+ PTX)
__device__ __forceinline__ ull f2pack(float lo, float hi) {
    ull r; asm("mov.b64 %0, {%1, %2};" : "=l"(r) : "f"(lo), "f"(hi)); return r;
}
__device__ __forceinline__ ull f2bcast(float v) {
    ull r; asm("mov.b64 %0, {%1, %1};" : "=l"(r) : "f"(v)); return r;
}
__device__ __forceinline__ ull f2fma(ull a, ull b, ull c) {
    ull d; asm("fma.rn.f32x2 %0, %1, %2, %3;" : "=l"(d) : "l"(a), "l"(b), "l"(c)); return d;
}
__device__ __forceinline__ float2 f2unpack(ull v) {
    float2 r; asm("mov.b64 {%0, %1}, %2;" : "=f"(r.x), "=f"(r.y) : "l"(v)); return r;
}

// ---------------- device scratch (no allocs allowed) ----------------
__device__ __align__(16) int    g_is64;
__device__ __align__(16) int    g_src32[EE];
__device__ __align__(16) int    g_dst32[EE];
__device__ __align__(16) int    g_deg[NN];
__device__ __align__(16) float  g_dis[NN];
__device__ __align__(16) int    g_ptmp[NN];
__device__ __align__(16) int    g_bsum[512];
__device__ __align__(16) int    g_boff[512];
__device__ __align__(16) int    g_rowptr[NN + 1];
__device__ __align__(16) int    g_cursor[NN];
__device__ __align__(16) int2   g_csre[EE];      // {src, norm (fp32 bits)}
__device__ __align__(16) __half g_h0h[NN * HH];  // x @ W1 (fp16)
__device__ __align__(16) float  g_t1[NN * HH];   // relu(agg1 + b1)
__device__ __align__(16) __half g_h1h[NN * HH];  // t1 @ W2 (fp16)
__device__ __align__(16) float  g_hf[NN * HH];   // agg2 + b2
__device__ __align__(16) __half g_ph[NN * HH];   // hf @ Wc1[0:64] + bc1 (fp16)
__device__ __align__(16) __half g_qh[NN * HH];   // hf @ Wc1[64:128]   (fp16)

// ---------------- detect index width + zero degrees (fused) ----------------
__global__ void k_detect_zero(const unsigned* __restrict__ w, int n) {
    int i = blockIdx.x * blockDim.x + threadIdx.x;
    if (i < n) g_deg[i] = 0;
    if (blockIdx.x == 0 && threadIdx.x < 32) {
        int lane = threadIdx.x;
        unsigned acc = 0;
        for (int j = 0; j < 32; j++) acc |= w[(lane * 32 + j) * 2 + 1];
        unsigned any = __ballot_sync(0xffffffffu, acc != 0);
        if (lane == 0) g_is64 = (any == 0u) ? 1 : 0;
    }
}

__global__ void k_convert(const void* __restrict__ ei, int E) {
    int e = blockIdx.x * blockDim.x + threadIdx.x;
    if (e >= 2 * E) return;
    int v;
    if (g_is64) v = (int)((const long long*)ei)[e];
    else        v = ((const int*)ei)[e];
    if (e < E) g_src32[e] = v;
    else { g_dst32[e - E] = v; atomicAdd(&g_deg[v], 1); }
}

// ---------------- scan1 (+ fused dis) ----------------
__global__ void k_scan1(int n) {
    __shared__ int sh[256];
    int i = blockIdx.x * 256 + threadIdx.x;
    int v = (i < n) ? g_deg[i] : 0;
    if (i < n) g_dis[i] = rsqrtf((float)(v + 1));
    sh[threadIdx.x] = v;
    __syncthreads();
    int acc = v;
#pragma unroll
    for (int o = 1; o < 256; o <<= 1) {
        int t = (threadIdx.x >= o) ? sh[threadIdx.x - o] : 0;
        __syncthreads();
        acc += t; sh[threadIdx.x] = acc;
        __syncthreads();
    }
    if (i < n) g_ptmp[i] = acc - v;
    if (threadIdx.x == 255) g_bsum[blockIdx.x] = acc;
}

__global__ void k_scan2(int nb) {
    __shared__ int sh[512];
    int t = threadIdx.x;
    int v = (t < nb) ? g_bsum[t] : 0;
    sh[t] = v;
    __syncthreads();
    int acc = v;
#pragma unroll
    for (int o = 1; o < 512; o <<= 1) {
        int x = (t >= o) ? sh[t - o] : 0;
        __syncthreads();
        acc += x; sh[t] = acc;
        __syncthreads();
    }
    if (t < nb) g_boff[t] = acc - v;
}

__global__ void k_scan3(int n, int E) {
    int i = blockIdx.x * 256 + threadIdx.x;
    if (i < n) {
        int r = g_ptmp[i] + g_boff[blockIdx.x];
        g_rowptr[i] = r;
        g_cursor[i] = r;
    }
    if (i == 0) g_rowptr[n] = E;
}

// ---------------- CSR fill: one STG.64 per edge ----------------
__global__ void k_fill(int E) {
    int e = blockIdx.x * 256 + threadIdx.x;
    if (e >= E) return;
    int s = g_src32[e];
    int d = g_dst32[e];
    int pos = atomicAdd(&g_cursor[d], 1);
    int2 v;
    v.x = s;
    v.y = __float_as_int(g_dis[s] * g_dis[d]);
    g_csre[pos] = v;
}

// ---------------- GEMM1: h0 = x @ W1 -> fp16 (f32x2 FMA) ----------------
// Ws interleaved: pair (col, col+32) adjacent -> one LDS.64 per k is a packed operand.
__global__ __launch_bounds__(256) void k_gemm1(const float* __restrict__ x,
                                               const float* __restrict__ W1, int n) {
    __shared__ float Ws[IC * HH];       // interleaved
    __shared__ float xs[8][4 * IC];
    int tid = threadIdx.x;
    for (int i = tid; i < IC * 32; i += 256) {
        int k = i >> 5, c = i & 31;
        ((float2*)Ws)[k * 32 + c] = make_float2(W1[k * HH + c], W1[k * HH + c + 32]);
    }
    __syncthreads();
    int w = tid >> 5, lane = tid & 31;
    int r0 = blockIdx.x * 32 + w * 4;
    if (r0 >= n) return;
    int nr = min(4, n - r0);
    const float4* xsrc = (const float4*)(x + (size_t)r0 * IC);
    float4* xd = (float4*)xs[w];
    for (int i = lane; i < nr * (IC / 4); i += 32) xd[i] = xsrc[i];
    __syncwarp();
    ull acc[4] = {0ull, 0ull, 0ull, 0ull};
    const ull* Wp = (const ull*)Ws;
#pragma unroll 8
    for (int k = 0; k < IC; k++) {
        ull wv = Wp[k * 32 + lane];
#pragma unroll
        for (int rr = 0; rr < 4; rr++) {
            ull xv = f2bcast(xs[w][rr * IC + k]);
            acc[rr] = f2fma(xv, wv, acc[rr]);
        }
    }
    for (int rr = 0; rr < nr; rr++) {
        int r = r0 + rr;
        float2 a = f2unpack(acc[rr]);
        g_h0h[r * HH + lane]      = __float2half(a.x);
        g_h0h[r * HH + lane + 32] = __float2half(a.y);
    }
}

// ---------------- CSR gather on fp16 rows (half2 lanes, 4-edge unroll) ----------------
template<int LAYER>
__global__ __launch_bounds__(256) void k_gather(const float* __restrict__ bias, int n) {
    int w = threadIdx.x >> 5, lane = threadIdx.x & 31;
    int node = blockIdx.x * 8 + w;
    if (node >= n) return;
    const __half2* h = (const __half2*)(LAYER ? g_h1h : g_h0h);
    float dd = g_dis[node];
    float d2 = dd * dd;
    float2 self = __half22float2(h[node * 32 + lane]);
    float ax = self.x * d2, ay = self.y * d2;
    int i = g_rowptr[node], end = g_rowptr[node + 1];
    for (; i + 4 <= end; i += 4) {
        int2 e0 = g_csre[i],     e1 = g_csre[i + 1];
        int2 e2 = g_csre[i + 2], e3 = g_csre[i + 3];
        float n0 = __int_as_float(e0.y), n1 = __int_as_float(e1.y);
        float n2 = __int_as_float(e2.y), n3 = __int_as_float(e3.y);
        float2 v0 = __half22float2(h[e0.x * 32 + lane]);
        float2 v1 = __half22float2(h[e1.x * 32 + lane]);
        float2 v2 = __half22float2(h[e2.x * 32 + lane]);
        float2 v3 = __half22float2(h[e3.x * 32 + lane]);
        ax = fmaf(v0.x, n0, ax); ay = fmaf(v0.y, n0, ay);
        ax = fmaf(v1.x, n1, ax); ay = fmaf(v1.y, n1, ay);
        ax = fmaf(v2.x, n2, ax); ay = fmaf(v2.y, n2, ay);
        ax = fmaf(v3.x, n3, ax); ay = fmaf(v3.y, n3, ay);
    }
    for (; i < end; i++) {
        int2 e0 = g_csre[i];
        float n0 = __int_as_float(e0.y);
        float2 v0 = __half22float2(h[e0.x * 32 + lane]);
        ax = fmaf(v0.x, n0, ax); ay = fmaf(v0.y, n0, ay);
    }
    float2 bb = __ldg((const float2*)bias + lane);
    float2 r;
    if (LAYER == 0) {
        r.x = fmaxf(ax + bb.x, 0.f);
        r.y = fmaxf(ay + bb.y, 0.f);
        ((float2*)g_t1)[node * 32 + lane] = r;
    } else {
        r.x = ax + bb.x;
        r.y = ay + bb.y;
        ((float2*)g_hf)[node * 32 + lane] = r;
    }
}

// ---------------- GEMM2: h1 = t1 @ W2 -> fp16 (f32x2 FMA) ----------------
__global__ __launch_bounds__(256) void k_gemm2(const float* __restrict__ W2, int n) {
    __shared__ float Ws[HH * HH];       // interleaved
    __shared__ float ts[8][4 * HH];
    int tid = threadIdx.x;
    for (int i = tid; i < HH * 32; i += 256) {
        int k = i >> 5, c = i & 31;
        ((float2*)Ws)[k * 32 + c] = make_float2(W2[k * HH + c], W2[k * HH + c + 32]);
    }
    __syncthreads();
    int w = tid >> 5, lane = tid & 31;
    int r0 = blockIdx.x * 32 + w * 4;
    if (r0 >= n) return;
    int nr = min(4, n - r0);
    const float4* tsrc = (const float4*)(g_t1 + (size_t)r0 * HH);
    float4* td = (float4*)ts[w];
    for (int i = lane; i < nr * (HH / 4); i += 32) td[i] = tsrc[i];
    __syncwarp();
    ull acc[4] = {0ull, 0ull, 0ull, 0ull};
    const ull* Wp = (const ull*)Ws;
#pragma unroll 8
    for (int k = 0; k < HH; k++) {
        ull wv = Wp[k * 32 + lane];
#pragma unroll
        for (int rr = 0; rr < 4; rr++) {
            ull tv = f2bcast(ts[w][rr * HH + k]);
            acc[rr] = f2fma(tv, wv, acc[rr]);
        }
    }
    for (int rr = 0; rr < nr; rr++) {
        int r = r0 + rr;
        float2 a = f2unpack(acc[rr]);
        g_h1h[r * HH + lane]      = __float2half(a.x);
        g_h1h[r * HH + lane + 32] = __float2half(a.y);
    }
}

// ---------------- p/q projection -> fp16, bc1 folded into p (f32x2 FMA) ----------------
__global__ __launch_bounds__(256) void k_pq(const float* __restrict__ Wc1,
                                            const float* __restrict__ bc1, int n) {
    __shared__ float Ws[2 * HH * HH];   // [0:HH*HH) p-half, [HH*HH:) q-half, interleaved
    __shared__ float hs[8][4 * HH];
    int tid = threadIdx.x;
    for (int i = tid; i < HH * 32; i += 256) {
        int k = i >> 5, c = i & 31;
        ((float2*)Ws)[k * 32 + c] =
            make_float2(Wc1[k * HH + c], Wc1[k * HH + c + 32]);
        ((float2*)(Ws + HH * HH))[k * 32 + c] =
            make_float2(Wc1[(HH + k) * HH + c], Wc1[(HH + k) * HH + c + 32]);
    }
    __syncthreads();
    int w = tid >> 5, lane = tid & 31;
    int r0 = blockIdx.x * 32 + w * 4;
    if (r0 >= n) return;
    int nr = min(4, n - r0);
    const float4* hsrc = (const float4*)(g_hf + (size_t)r0 * HH);
    float4* hd = (float4*)hs[w];
    for (int i = lane; i < nr * (HH / 4); i += 32) hd[i] = hsrc[i];
    __syncwarp();
    ull ap[4] = {0ull, 0ull, 0ull, 0ull};
    ull aq[4] = {0ull, 0ull, 0ull, 0ull};
    const ull* Wpp = (const ull*)Ws;
    const ull* Wqq = (const ull*)(Ws + HH * HH);
#pragma unroll 4
    for (int k = 0; k < HH; k++) {
        ull wp = Wpp[k * 32 + lane];
        ull wq = Wqq[k * 32 + lane];
#pragma unroll
        for (int rr = 0; rr < 4; rr++) {
            ull hv = f2bcast(hs[w][rr * HH + k]);
            ap[rr] = f2fma(hv, wp, ap[rr]);
            aq[rr] = f2fma(hv, wq, aq[rr]);
        }
    }
    float c0 = __ldg(&bc1[lane]), c1 = __ldg(&bc1[lane + 32]);
    for (int rr = 0; rr < nr; rr++) {
        int r = r0 + rr;
        float2 a = f2unpack(ap[rr]);
        float2 b = f2unpack(aq[rr]);
        g_ph[r * HH + lane]      = __float2half(a.x + c0);
        g_ph[r * HH + lane + 32] = __float2half(a.y + c1);
        g_qh[r * HH + lane]      = __float2half(b.x);
        g_qh[r * HH + lane + 32] = __float2half(b.y);
    }
}

// ---------------- edge classifier: 8 lanes/edge, LDG.128 fp16 rows ----------------
__global__ __launch_bounds__(256) void k_cls(const float* __restrict__ Wc2,
                                             const float* __restrict__ bc2,
                                             float2* __restrict__ out, int E) {
    int t = blockIdx.x * 256 + threadIdx.x;
    int e = t >> 3;
    if (e >= E) return;
    int l = t & 7;
    int s = g_src32[e];
    int d = g_dst32[e];
    uint4 pv = *(const uint4*)(g_ph + (size_t)s * HH + l * 8);
    uint4 qv = *(const uint4*)(g_qh + (size_t)d * HH + l * 8);
    const __half2* pp = (const __half2*)&pv;
    const __half2* qq = (const __half2*)&qv;
    float s0 = 0.f, s1 = 0.f;
#pragma unroll
    for (int j = 0; j < 4; j++) {
        float2 a = __half22float2(pp[j]);
        float2 b = __half22float2(qq[j]);
        float u0 = fmaxf(a.x + b.x, 0.f);
        float u1 = fmaxf(a.y + b.y, 0.f);
        int c = l * 8 + j * 2;
        float2 wA = __ldg((const float2*)Wc2 + c);
        float2 wB = __ldg((const float2*)Wc2 + c + 1);
        s0 += u0 * wA.x + u1 * wB.x;
        s1 += u0 * wA.y + u1 * wB.y;
    }
#pragma unroll
    for (int o = 4; o > 0; o >>= 1) {
        s0 += __shfl_down_sync(0xffffffffu, s0, o, 8);
        s1 += __shfl_down_sync(0xffffffffu, s1, o, 8);
    }
    if (l == 0) {
        float2 r;
        r.x = s0 + __ldg(&bc2[0]);
        r.y = s1 + __ldg(&bc2[1]);
        out[e] = r;
    }
}

// ---------------- launch ----------------
extern "C" void kernel_launch(void* const* d_in, const int* in_sizes, int n_in,
                              void* d_out, int out_size) {
    const float* x   = (const float*)d_in[0];
    const void*  ei  = d_in[1];
    const float* W1  = (const float*)d_in[2];
    const float* b1  = (const float*)d_in[3];
    const float* W2  = (const float*)d_in[4];
    const float* b2  = (const float*)d_in[5];
    const float* Wc1 = (const float*)d_in[6];
    const float* bc1 = (const float*)d_in[7];
    const float* Wc2 = (const float*)d_in[8];
    const float* bc2 = (const float*)d_in[9];

    int N = in_sizes[0] / IC;   // 100000
    int E = in_sizes[1] / 2;    // 1600000
    int nb = (N + 255) / 256;

    k_detect_zero<<<nb, 256>>>((const unsigned*)ei, N);
    k_convert<<<(2 * E + 255) / 256, 256>>>(ei, E);
    k_scan1<<<nb, 256>>>(N);
    k_scan2<<<1, 512>>>(nb);
    k_scan3<<<nb, 256>>>(N, E);
    k_fill<<<(E + 255) / 256, 256>>>(E);

    k_gemm1<<<(N + 31) / 32, 256>>>(x, W1, N);
    k_gather<0><<<(N + 7) / 8, 256>>>(b1, N);
    k_gemm2<<<(N + 31) / 32, 256>>>(W2, N);
    k_gather<1><<<(N + 7) / 8, 256>>>(b2, N);
    k_pq<<<(N + 31) / 32, 256>>>(Wc1, bc1, N);
    k_cls<<<(int)(((long long)E * 8 + 255) / 256), 256>>>(Wc2, bc2, (float2*)d_out, E);
}

// round 11
// speedup vs baseline: 1.0292x; 1.0292x over previous
#include <cuda_runtime.h>
#include <cuda_fp16.h>

#define NN 100000
#define EE 1600000
#define IC 128
#define HH 64

// ---------------- device scratch (no allocs allowed) ----------------
__device__ __align__(16) int    g_deg[NN];
__device__ __align__(16) float  g_dis[NN];
__device__ __align__(16) int    g_ptmp[NN];
__device__ __align__(16) int    g_bsum[512];
__device__ __align__(16) int    g_boff[512];
__device__ __align__(16) int    g_rowptr[NN + 1];
__device__ __align__(16) int    g_cursor[NN];
__device__ __align__(16) int2   g_csre[EE];      // {src, norm (fp32 bits)}
__device__ __align__(16) __half g_h0h[NN * HH];  // x @ W1 (fp16)
__device__ __align__(16) float  g_t1[NN * HH];   // relu(agg1 + b1)
__device__ __align__(16) __half g_h1h[NN * HH];  // t1 @ W2 (fp16)
__device__ __align__(16) float  g_hf[NN * HH];   // agg2 + b2
__device__ __align__(16) __half g_ph[NN * HH];   // hf @ Wc1[0:64] + bc1 (fp16)
__device__ __align__(16) __half g_qh[NN * HH];   // hf @ Wc1[64:128]   (fp16)

// ---------------- GEMM1: h0 = x @ W1 -> fp16 ; prologue zeroes g_deg ----------------
__global__ __launch_bounds__(256) void k_gemm1(const float* __restrict__ x,
                                               const float* __restrict__ W1, int n) {
    // fused deg zeroing (blocks 0..390 cover 100096 >= NN)
    {
        int i = blockIdx.x * 256 + threadIdx.x;
        if (i < n) g_deg[i] = 0;
    }
    __shared__ float Ws[IC * HH];
    __shared__ float xs[8][4 * IC];
    int tid = threadIdx.x;
    for (int i = tid; i < IC * HH / 4; i += 256)
        ((float4*)Ws)[i] = ((const float4*)W1)[i];
    __syncthreads();
    int w = tid >> 5, lane = tid & 31;
    int r0 = blockIdx.x * 32 + w * 4;
    if (r0 >= n) return;
    int nr = min(4, n - r0);
    const float4* xsrc = (const float4*)(x + (size_t)r0 * IC);
    float4* xd = (float4*)xs[w];
    for (int i = lane; i < nr * (IC / 4); i += 32) xd[i] = xsrc[i];
    __syncwarp();
    float acc[4][2] = {};
#pragma unroll 8
    for (int k = 0; k < IC; k++) {
        float w0 = Ws[k * HH + lane], w1 = Ws[k * HH + lane + 32];
#pragma unroll
        for (int rr = 0; rr < 4; rr++) {
            float xv = xs[w][rr * IC + k];
            acc[rr][0] = fmaf(xv, w0, acc[rr][0]);
            acc[rr][1] = fmaf(xv, w1, acc[rr][1]);
        }
    }
    for (int rr = 0; rr < nr; rr++) {
        int r = r0 + rr;
        g_h0h[r * HH + lane]      = __float2half(acc[rr][0]);
        g_h0h[r * HH + lane + 32] = __float2half(acc[rr][1]);
    }
}

// ---------------- degree histogram straight off the input buffer ----------------
__global__ void k_deg(const int* __restrict__ ei, int E) {
    int e = blockIdx.x * blockDim.x + threadIdx.x;
    if (e < E) atomicAdd(&g_deg[ei[E + e]], 1);
}

// ---------------- scan1 (+ fused dis) ----------------
__global__ void k_scan1(int n) {
    __shared__ int sh[256];
    int i = blockIdx.x * 256 + threadIdx.x;
    int v = (i < n) ? g_deg[i] : 0;
    if (i < n) g_dis[i] = rsqrtf((float)(v + 1));
    sh[threadIdx.x] = v;
    __syncthreads();
    int acc = v;
#pragma unroll
    for (int o = 1; o < 256; o <<= 1) {
        int t = (threadIdx.x >= o) ? sh[threadIdx.x - o] : 0;
        __syncthreads();
        acc += t; sh[threadIdx.x] = acc;
        __syncthreads();
    }
    if (i < n) g_ptmp[i] = acc - v;
    if (threadIdx.x == 255) g_bsum[blockIdx.x] = acc;
}

__global__ void k_scan2(int nb) {
    __shared__ int sh[512];
    int t = threadIdx.x;
    int v = (t < nb) ? g_bsum[t] : 0;
    sh[t] = v;
    __syncthreads();
    int acc = v;
#pragma unroll
    for (int o = 1; o < 512; o <<= 1) {
        int x = (t >= o) ? sh[t - o] : 0;
        __syncthreads();
        acc += x; sh[t] = acc;
        __syncthreads();
    }
    if (t < nb) g_boff[t] = acc - v;
}

__global__ void k_scan3(int n, int E) {
    int i = blockIdx.x * 256 + threadIdx.x;
    if (i < n) {
        int r = g_ptmp[i] + g_boff[blockIdx.x];
        g_rowptr[i] = r;
        g_cursor[i] = r;
    }
    if (i == 0) g_rowptr[n] = E;
}

// ---------------- CSR fill: one STG.64 per edge, reads input buffer ----------------
__global__ void k_fill(const int* __restrict__ ei, int E) {
    int e = blockIdx.x * 256 + threadIdx.x;
    if (e >= E) return;
    int s = ei[e];
    int d = ei[E + e];
    int pos = atomicAdd(&g_cursor[d], 1);
    int2 v;
    v.x = s;
    v.y = __float_as_int(g_dis[s] * g_dis[d]);
    g_csre[pos] = v;
}

// ---------------- CSR gather on fp16 rows (half2 lanes, 4-edge unroll) ----------------
template<int LAYER>
__global__ __launch_bounds__(256) void k_gather(const float* __restrict__ bias, int n) {
    int w = threadIdx.x >> 5, lane = threadIdx.x & 31;
    int node = blockIdx.x * 8 + w;
    if (node >= n) return;
    const __half2* h = (const __half2*)(LAYER ? g_h1h : g_h0h);
    float dd = g_dis[node];
    float d2 = dd * dd;
    float2 self = __half22float2(h[node * 32 + lane]);
    float ax = self.x * d2, ay = self.y * d2;
    int i = g_rowptr[node], end = g_rowptr[node + 1];
    for (; i + 4 <= end; i += 4) {
        int2 e0 = g_csre[i],     e1 = g_csre[i + 1];
        int2 e2 = g_csre[i + 2], e3 = g_csre[i + 3];
        float n0 = __int_as_float(e0.y), n1 = __int_as_float(e1.y);
        float n2 = __int_as_float(e2.y), n3 = __int_as_float(e3.y);
        float2 v0 = __half22float2(h[e0.x * 32 + lane]);
        float2 v1 = __half22float2(h[e1.x * 32 + lane]);
        float2 v2 = __half22float2(h[e2.x * 32 + lane]);
        float2 v3 = __half22float2(h[e3.x * 32 + lane]);
        ax = fmaf(v0.x, n0, ax); ay = fmaf(v0.y, n0, ay);
        ax = fmaf(v1.x, n1, ax); ay = fmaf(v1.y, n1, ay);
        ax = fmaf(v2.x, n2, ax); ay = fmaf(v2.y, n2, ay);
        ax = fmaf(v3.x, n3, ax); ay = fmaf(v3.y, n3, ay);
    }
    for (; i < end; i++) {
        int2 e0 = g_csre[i];
        float n0 = __int_as_float(e0.y);
        float2 v0 = __half22float2(h[e0.x * 32 + lane]);
        ax = fmaf(v0.x, n0, ax); ay = fmaf(v0.y, n0, ay);
    }
    float2 bb = __ldg((const float2*)bias + lane);
    float2 r;
    if (LAYER == 0) {
        r.x = fmaxf(ax + bb.x, 0.f);
        r.y = fmaxf(ay + bb.y, 0.f);
        ((float2*)g_t1)[node * 32 + lane] = r;
    } else {
        r.x = ax + bb.x;
        r.y = ay + bb.y;
        ((float2*)g_hf)[node * 32 + lane] = r;
    }
}

// ---------------- GEMM2: h1 = t1 @ W2 -> fp16 ----------------
__global__ __launch_bounds__(256) void k_gemm2(const float* __restrict__ W2, int n) {
    __shared__ float Ws[HH * HH];
    __shared__ float ts[8][4 * HH];
    int tid = threadIdx.x;
    for (int i = tid; i < HH * HH / 4; i += 256)
        ((float4*)Ws)[i] = ((const float4*)W2)[i];
    __syncthreads();
    int w = tid >> 5, lane = tid & 31;
    int r0 = blockIdx.x * 32 + w * 4;
    if (r0 >= n) return;
    int nr = min(4, n - r0);
    const float4* tsrc = (const float4*)(g_t1 + (size_t)r0 * HH);
    float4* td = (float4*)ts[w];
    for (int i = lane; i < nr * (HH / 4); i += 32) td[i] = tsrc[i];
    __syncwarp();
    float acc[4][2] = {};
#pragma unroll 8
    for (int k = 0; k < HH; k++) {
        float w0 = Ws[k * HH + lane], w1 = Ws[k * HH + lane + 32];
#pragma unroll
        for (int rr = 0; rr < 4; rr++) {
            float tv = ts[w][rr * HH + k];
            acc[rr][0] = fmaf(tv, w0, acc[rr][0]);
            acc[rr][1] = fmaf(tv, w1, acc[rr][1]);
        }
    }
    for (int rr = 0; rr < nr; rr++) {
        int r = r0 + rr;
        g_h1h[r * HH + lane]      = __float2half(acc[rr][0]);
        g_h1h[r * HH + lane + 32] = __float2half(acc[rr][1]);
    }
}

// ---------------- p/q projection -> fp16, bc1 folded into p ----------------
__global__ __launch_bounds__(256) void k_pq(const float* __restrict__ Wc1,
                                            const float* __restrict__ bc1, int n) {
    __shared__ float Ws[2 * HH * HH];
    __shared__ float hs[8][4 * HH];
    int tid = threadIdx.x;
    for (int i = tid; i < 2 * HH * HH / 4; i += 256)
        ((float4*)Ws)[i] = ((const float4*)Wc1)[i];
    __syncthreads();
    int w = tid >> 5, lane = tid & 31;
    int r0 = blockIdx.x * 32 + w * 4;
    if (r0 >= n) return;
    int nr = min(4, n - r0);
    const float4* hsrc = (const float4*)(g_hf + (size_t)r0 * HH);
    float4* hd = (float4*)hs[w];
    for (int i = lane; i < nr * (HH / 4); i += 32) hd[i] = hsrc[i];
    __syncwarp();
    float ap[4][2] = {}, aq[4][2] = {};
#pragma unroll 4
    for (int k = 0; k < HH; k++) {
        float wp0 = Ws[k * HH + lane],        wp1 = Ws[k * HH + lane + 32];
        float wq0 = Ws[(HH + k) * HH + lane], wq1 = Ws[(HH + k) * HH + lane + 32];
#pragma unroll
        for (int rr = 0; rr < 4; rr++) {
            float hv = hs[w][rr * HH + k];
            ap[rr][0] = fmaf(hv, wp0, ap[rr][0]);
            ap[rr][1] = fmaf(hv, wp1, ap[rr][1]);
            aq[rr][0] = fmaf(hv, wq0, aq[rr][0]);
            aq[rr][1] = fmaf(hv, wq1, aq[rr][1]);
        }
    }
    float c0 = __ldg(&bc1[lane]), c1 = __ldg(&bc1[lane + 32]);
    for (int rr = 0; rr < nr; rr++) {
        int r = r0 + rr;
        g_ph[r * HH + lane]      = __float2half(ap[rr][0] + c0);
        g_ph[r * HH + lane + 32] = __float2half(ap[rr][1] + c1);
        g_qh[r * HH + lane]      = __float2half(aq[rr][0]);
        g_qh[r * HH + lane + 32] = __float2half(aq[rr][1]);
    }
}

// ---------------- edge classifier: 8 lanes/edge, LDG.128 fp16 rows ----------------
__global__ __launch_bounds__(256) void k_cls(const int* __restrict__ ei,
                                             const float* __restrict__ Wc2,
                                             const float* __restrict__ bc2,
                                             float2* __restrict__ out, int E) {
    int t = blockIdx.x * 256 + threadIdx.x;
    int e = t >> 3;
    if (e >= E) return;
    int l = t & 7;
    int s = __ldg(&ei[e]);
    int d = __ldg(&ei[E + e]);
    uint4 pv = *(const uint4*)(g_ph + (size_t)s * HH + l * 8);
    uint4 qv = *(const uint4*)(g_qh + (size_t)d * HH + l * 8);
    const __half2* pp = (const __half2*)&pv;
    const __half2* qq = (const __half2*)&qv;
    float s0 = 0.f, s1 = 0.f;
#pragma unroll
    for (int j = 0; j < 4; j++) {
        float2 a = __half22float2(pp[j]);
        float2 b = __half22float2(qq[j]);
        float u0 = fmaxf(a.x + b.x, 0.f);
        float u1 = fmaxf(a.y + b.y, 0.f);
        int c = l * 8 + j * 2;
        float2 wA = __ldg((const float2*)Wc2 + c);
        float2 wB = __ldg((const float2*)Wc2 + c + 1);
        s0 += u0 * wA.x + u1 * wB.x;
        s1 += u0 * wA.y + u1 * wB.y;
    }
#pragma unroll
    for (int o = 4; o > 0; o >>= 1) {
        s0 += __shfl_down_sync(0xffffffffu, s0, o, 8);
        s1 += __shfl_down_sync(0xffffffffu, s1, o, 8);
    }
    if (l == 0) {
        float2 r;
        r.x = s0 + __ldg(&bc2[0]);
        r.y = s1 + __ldg(&bc2[1]);
        out[e] = r;
    }
}

// ---------------- launch ----------------
extern "C" void kernel_launch(void* const* d_in, const int* in_sizes, int n_in,
                              void* d_out, int out_size) {
    const float* x   = (const float*)d_in[0];
    const int*   ei  = (const int*)d_in[1];   // int32 edge_index (verified R4-R10)
    const float* W1  = (const float*)d_in[2];
    const float* b1  = (const float*)d_in[3];
    const float* W2  = (const float*)d_in[4];
    const float* b2  = (const float*)d_in[5];
    const float* Wc1 = (const float*)d_in[6];
    const float* bc1 = (const float*)d_in[7];
    const float* Wc2 = (const float*)d_in[8];
    const float* bc2 = (const float*)d_in[9];

    int N = in_sizes[0] / IC;   // 100000
    int E = in_sizes[1] / 2;    // 1600000
    int nb = (N + 255) / 256;

    // gemm1 zeroes g_deg in its prologue and is independent of graph data
    k_gemm1<<<(N + 31) / 32, 256>>>(x, W1, N);
    k_deg<<<(E + 255) / 256, 256>>>(ei, E);
    k_scan1<<<nb, 256>>>(N);
    k_scan2<<<1, 512>>>(nb);
    k_scan3<<<nb, 256>>>(N, E);
    k_fill<<<(E + 255) / 256, 256>>>(ei, E);

    k_gather<0><<<(N + 7) / 8, 256>>>(b1, N);
    k_gemm2<<<(N + 31) / 32, 256>>>(W2, N);
    k_gather<1><<<(N + 7) / 8, 256>>>(b2, N);
    k_pq<<<(N + 31) / 32, 256>>>(Wc1, bc1, N);
    k_cls<<<(int)(((long long)E * 8 + 255) / 256), 256>>>(ei, Wc2, bc2, (float2*)d_out, E);
}

// round 12
// speedup vs baseline: 1.0980x; 1.0668x over previous
#include <cuda_runtime.h>
#include <cuda_fp16.h>

#define NN 100000
#define EE 1600000
#define IC 128
#define HH 64

// ---------------- device scratch (no allocs allowed) ----------------
__device__ __align__(16) int    g_deg[NN];
__device__ __align__(16) float  g_dis[NN];
__device__ __align__(16) int    g_ptmp[NN];
__device__ __align__(16) int    g_bsum[512];
__device__ __align__(16) int    g_boff[512];
__device__ __align__(16) int    g_rowptr[NN + 1];
__device__ __align__(16) int    g_cursor[NN];
__device__ __align__(16) int2   g_csre[EE];      // {src, norm (fp32 bits)}
__device__ __align__(16) __half g_h0h[NN * HH];  // x @ W1 (fp16)
__device__ __align__(16) __half g_t1h[NN * HH];  // relu(agg1 + b1) (fp16)
__device__ __align__(16) float  g_at[NN * HH];   // agg2 of t1 (fp32, pre-W2)
__device__ __align__(16) __half g_ph[NN * HH];   // p (fp16, bias folded)
__device__ __align__(16) __half g_qh[NN * HH];   // q (fp16, bias folded)
__device__ __align__(16) float  g_Wpq[2 * HH * HH]; // [Wp | Wq] = W2 @ [Wc1_top | Wc1_bot]
__device__ __align__(16) float  g_bp[HH];
__device__ __align__(16) float  g_bq[HH];

// ---------------- GEMM1: h0 = x @ W1 -> fp16 ; prologue zeroes g_deg ----------------
__global__ __launch_bounds__(256) void k_gemm1(const float* __restrict__ x,
                                               const float* __restrict__ W1, int n) {
    {
        int i = blockIdx.x * 256 + threadIdx.x;
        if (i < n) g_deg[i] = 0;
    }
    __shared__ float Ws[IC * HH];
    __shared__ float xs[8][4 * IC];
    int tid = threadIdx.x;
    for (int i = tid; i < IC * HH / 4; i += 256)
        ((float4*)Ws)[i] = ((const float4*)W1)[i];
    __syncthreads();
    int w = tid >> 5, lane = tid & 31;
    int r0 = blockIdx.x * 32 + w * 4;
    if (r0 >= n) return;
    int nr = min(4, n - r0);
    const float4* xsrc = (const float4*)(x + (size_t)r0 * IC);
    float4* xd = (float4*)xs[w];
    for (int i = lane; i < nr * (IC / 4); i += 32) xd[i] = xsrc[i];
    __syncwarp();
    float acc[4][2] = {};
#pragma unroll 8
    for (int k = 0; k < IC; k++) {
        float w0 = Ws[k * HH + lane], w1 = Ws[k * HH + lane + 32];
#pragma unroll
        for (int rr = 0; rr < 4; rr++) {
            float xv = xs[w][rr * IC + k];
            acc[rr][0] = fmaf(xv, w0, acc[rr][0]);
            acc[rr][1] = fmaf(xv, w1, acc[rr][1]);
        }
    }
    for (int rr = 0; rr < nr; rr++) {
        int r = r0 + rr;
        g_h0h[r * HH + lane]      = __float2half(acc[rr][0]);
        g_h0h[r * HH + lane + 32] = __float2half(acc[rr][1]);
    }
}

// ---------------- weight pre-combination: Wpq = W2 @ [Wc1_top | Wc1_bot] ----------------
// 8 blocks; block b handles k in [b*8, b*8+8). Block 0 also does biases.
__global__ __launch_bounds__(256) void k_wcomb(const float* __restrict__ W2,
                                               const float* __restrict__ b2,
                                               const float* __restrict__ Wc1,
                                               const float* __restrict__ bc1) {
    __shared__ float sW2[HH * HH];       // 16 KB
    __shared__ float sWc1[2 * HH * HH];  // 32 KB
    int tid = threadIdx.x;
    for (int i = tid; i < HH * HH / 4; i += 256)
        ((float4*)sW2)[i] = ((const float4*)W2)[i];
    for (int i = tid; i < 2 * HH * HH / 4; i += 256)
        ((float4*)sWc1)[i] = ((const float4*)Wc1)[i];
    __syncthreads();
    int kbase = blockIdx.x * 8;  // 8 k-rows per block
    for (int idx = tid; idx < 8 * HH; idx += 256) {
        int k = kbase + (idx >> 6), c = idx & 63;
        float sp = 0.f, sq = 0.f;
#pragma unroll 8
        for (int j = 0; j < HH; j++) {
            float w = sW2[k * HH + j];
            sp = fmaf(w, sWc1[j * HH + c], sp);
            sq = fmaf(w, sWc1[(HH + j) * HH + c], sq);
        }
        g_Wpq[k * HH + c]           = sp;
        g_Wpq[HH * HH + k * HH + c] = sq;
    }
    if (blockIdx.x == 0 && tid < HH) {
        float sp = bc1[tid], sq = 0.f;
        for (int j = 0; j < HH; j++) {
            float b = b2[j];
            sp = fmaf(b, sWc1[j * HH + tid], sp);
            sq = fmaf(b, sWc1[(HH + j) * HH + tid], sq);
        }
        g_bp[tid] = sp;
        g_bq[tid] = sq;
    }
}

// ---------------- degree histogram straight off the input buffer ----------------
__global__ void k_deg(const int* __restrict__ ei, int E) {
    int e = blockIdx.x * blockDim.x + threadIdx.x;
    if (e < E) atomicAdd(&g_deg[ei[E + e]], 1);
}

// ---------------- scan1 (+ fused dis) ----------------
__global__ void k_scan1(int n) {
    __shared__ int sh[256];
    int i = blockIdx.x * 256 + threadIdx.x;
    int v = (i < n) ? g_deg[i] : 0;
    if (i < n) g_dis[i] = rsqrtf((float)(v + 1));
    sh[threadIdx.x] = v;
    __syncthreads();
    int acc = v;
#pragma unroll
    for (int o = 1; o < 256; o <<= 1) {
        int t = (threadIdx.x >= o) ? sh[threadIdx.x - o] : 0;
        __syncthreads();
        acc += t; sh[threadIdx.x] = acc;
        __syncthreads();
    }
    if (i < n) g_ptmp[i] = acc - v;
    if (threadIdx.x == 255) g_bsum[blockIdx.x] = acc;
}

__global__ void k_scan2(int nb) {
    __shared__ int sh[512];
    int t = threadIdx.x;
    int v = (t < nb) ? g_bsum[t] : 0;
    sh[t] = v;
    __syncthreads();
    int acc = v;
#pragma unroll
    for (int o = 1; o < 512; o <<= 1) {
        int x = (t >= o) ? sh[t - o] : 0;
        __syncthreads();
        acc += x; sh[t] = acc;
        __syncthreads();
    }
    if (t < nb) g_boff[t] = acc - v;
}

__global__ void k_scan3(int n, int E) {
    int i = blockIdx.x * 256 + threadIdx.x;
    if (i < n) {
        int r = g_ptmp[i] + g_boff[blockIdx.x];
        g_rowptr[i] = r;
        g_cursor[i] = r;
    }
    if (i == 0) g_rowptr[n] = E;
}

// ---------------- CSR fill: one STG.64 per edge ----------------
__global__ void k_fill(const int* __restrict__ ei, int E) {
    int e = blockIdx.x * 256 + threadIdx.x;
    if (e >= E) return;
    int s = ei[e];
    int d = ei[E + e];
    int pos = atomicAdd(&g_cursor[d], 1);
    int2 v;
    v.x = s;
    v.y = __float_as_int(g_dis[s] * g_dis[d]);
    g_csre[pos] = v;
}

// ---------------- CSR gather on fp16 rows (half2 lanes, 4-edge unroll) ----------------
// LAYER 0: h = h0h, out = t1h = fp16(relu(acc + b1))
// LAYER 1: h = t1h, out = g_at = fp32(acc)       (bias handled later, folded)
template<int LAYER>
__global__ __launch_bounds__(256) void k_gather(const float* __restrict__ bias, int n) {
    int w = threadIdx.x >> 5, lane = threadIdx.x & 31;
    int node = blockIdx.x * 8 + w;
    if (node >= n) return;
    const __half2* h = (const __half2*)(LAYER ? g_t1h : g_h0h);
    float dd = g_dis[node];
    float d2 = dd * dd;
    float2 self = __half22float2(h[node * 32 + lane]);
    float ax = self.x * d2, ay = self.y * d2;
    int i = g_rowptr[node], end = g_rowptr[node + 1];
    for (; i + 4 <= end; i += 4) {
        int2 e0 = g_csre[i],     e1 = g_csre[i + 1];
        int2 e2 = g_csre[i + 2], e3 = g_csre[i + 3];
        float n0 = __int_as_float(e0.y), n1 = __int_as_float(e1.y);
        float n2 = __int_as_float(e2.y), n3 = __int_as_float(e3.y);
        float2 v0 = __half22float2(h[e0.x * 32 + lane]);
        float2 v1 = __half22float2(h[e1.x * 32 + lane]);
        float2 v2 = __half22float2(h[e2.x * 32 + lane]);
        float2 v3 = __half22float2(h[e3.x * 32 + lane]);
        ax = fmaf(v0.x, n0, ax); ay = fmaf(v0.y, n0, ay);
        ax = fmaf(v1.x, n1, ax); ay = fmaf(v1.y, n1, ay);
        ax = fmaf(v2.x, n2, ax); ay = fmaf(v2.y, n2, ay);
        ax = fmaf(v3.x, n3, ax); ay = fmaf(v3.y, n3, ay);
    }
    for (; i < end; i++) {
        int2 e0 = g_csre[i];
        float n0 = __int_as_float(e0.y);
        float2 v0 = __half22float2(h[e0.x * 32 + lane]);
        ax = fmaf(v0.x, n0, ax); ay = fmaf(v0.y, n0, ay);
    }
    if (LAYER == 0) {
        float2 bb = __ldg((const float2*)bias + lane);
        float rx = fmaxf(ax + bb.x, 0.f);
        float ry = fmaxf(ay + bb.y, 0.f);
        ((__half2*)g_t1h)[node * 32 + lane] = __floats2half2_rn(rx, ry);
    } else {
        float2 r; r.x = ax; r.y = ay;
        ((float2*)g_at)[node * 32 + lane] = r;
    }
}

// ---------------- p/q projection from aggt with pre-combined weights ----------------
__global__ __launch_bounds__(256) void k_pqc(int n) {
    __shared__ float Ws[2 * HH * HH];
    __shared__ float hs[8][4 * HH];
    int tid = threadIdx.x;
    for (int i = tid; i < 2 * HH * HH / 4; i += 256)
        ((float4*)Ws)[i] = ((const float4*)g_Wpq)[i];
    __syncthreads();
    int w = tid >> 5, lane = tid & 31;
    int r0 = blockIdx.x * 32 + w * 4;
    if (r0 >= n) return;
    int nr = min(4, n - r0);
    const float4* hsrc = (const float4*)(g_at + (size_t)r0 * HH);
    float4* hd = (float4*)hs[w];
    for (int i = lane; i < nr * (HH / 4); i += 32) hd[i] = hsrc[i];
    __syncwarp();
    float ap[4][2] = {}, aq[4][2] = {};
#pragma unroll 4
    for (int k = 0; k < HH; k++) {
        float wp0 = Ws[k * HH + lane],        wp1 = Ws[k * HH + lane + 32];
        float wq0 = Ws[(HH + k) * HH + lane], wq1 = Ws[(HH + k) * HH + lane + 32];
#pragma unroll
        for (int rr = 0; rr < 4; rr++) {
            float hv = hs[w][rr * HH + k];
            ap[rr][0] = fmaf(hv, wp0, ap[rr][0]);
            ap[rr][1] = fmaf(hv, wp1, ap[rr][1]);
            aq[rr][0] = fmaf(hv, wq0, aq[rr][0]);
            aq[rr][1] = fmaf(hv, wq1, aq[rr][1]);
        }
    }
    float p0 = g_bp[lane], p1 = g_bp[lane + 32];
    float q0 = g_bq[lane], q1 = g_bq[lane + 32];
    for (int rr = 0; rr < nr; rr++) {
        int r = r0 + rr;
        g_ph[r * HH + lane]      = __float2half(ap[rr][0] + p0);
        g_ph[r * HH + lane + 32] = __float2half(ap[rr][1] + p1);
        g_qh[r * HH + lane]      = __float2half(aq[rr][0] + q0);
        g_qh[r * HH + lane + 32] = __float2half(aq[rr][1] + q1);
    }
}

// ---------------- edge classifier: 8 lanes/edge, LDG.128 fp16 rows ----------------
__global__ __launch_bounds__(256) void k_cls(const int* __restrict__ ei,
                                             const float* __restrict__ Wc2,
                                             const float* __restrict__ bc2,
                                             float2* __restrict__ out, int E) {
    int t = blockIdx.x * 256 + threadIdx.x;
    int e = t >> 3;
    if (e >= E) return;
    int l = t & 7;
    int s = __ldg(&ei[e]);
    int d = __ldg(&ei[E + e]);
    uint4 pv = *(const uint4*)(g_ph + (size_t)s * HH + l * 8);
    uint4 qv = *(const uint4*)(g_qh + (size_t)d * HH + l * 8);
    const __half2* pp = (const __half2*)&pv;
    const __half2* qq = (const __half2*)&qv;
    float s0 = 0.f, s1 = 0.f;
#pragma unroll
    for (int j = 0; j < 4; j++) {
        float2 a = __half22float2(pp[j]);
        float2 b = __half22float2(qq[j]);
        float u0 = fmaxf(a.x + b.x, 0.f);
        float u1 = fmaxf(a.y + b.y, 0.f);
        int c = l * 8 + j * 2;
        float2 wA = __ldg((const float2*)Wc2 + c);
        float2 wB = __ldg((const float2*)Wc2 + c + 1);
        s0 += u0 * wA.x + u1 * wB.x;
        s1 += u0 * wA.y + u1 * wB.y;
    }
#pragma unroll
    for (int o = 4; o > 0; o >>= 1) {
        s0 += __shfl_down_sync(0xffffffffu, s0, o, 8);
        s1 += __shfl_down_sync(0xffffffffu, s1, o, 8);
    }
    if (l == 0) {
        float2 r;
        r.x = s0 + __ldg(&bc2[0]);
        r.y = s1 + __ldg(&bc2[1]);
        out[e] = r;
    }
}

// ---------------- launch ----------------
extern "C" void kernel_launch(void* const* d_in, const int* in_sizes, int n_in,
                              void* d_out, int out_size) {
    const float* x   = (const float*)d_in[0];
    const int*   ei  = (const int*)d_in[1];   // int32 edge_index (verified R4+)
    const float* W1  = (const float*)d_in[2];
    const float* b1  = (const float*)d_in[3];
    const float* W2  = (const float*)d_in[4];
    const float* b2  = (const float*)d_in[5];
    const float* Wc1 = (const float*)d_in[6];
    const float* bc1 = (const float*)d_in[7];
    const float* Wc2 = (const float*)d_in[8];
    const float* bc2 = (const float*)d_in[9];

    int N = in_sizes[0] / IC;   // 100000
    int E = in_sizes[1] / 2;    // 1600000
    int nb = (N + 255) / 256;

    k_gemm1<<<(N + 31) / 32, 256>>>(x, W1, N);       // + zeroes g_deg
    k_wcomb<<<8, 256>>>(W2, b2, Wc1, bc1);           // independent of graph
    k_deg<<<(E + 255) / 256, 256>>>(ei, E);
    k_scan1<<<nb, 256>>>(N);
    k_scan2<<<1, 512>>>(nb);
    k_scan3<<<nb, 256>>>(N, E);
    k_fill<<<(E + 255) / 256, 256>>>(ei, E);

    k_gather<0><<<(N + 7) / 8, 256>>>(b1, N);
    k_gather<1><<<(N + 7) / 8, 256>>>(nullptr, N);
    k_pqc<<<(N + 31) / 32, 256>>>(N);
    k_cls<<<(int)(((long long)E * 8 + 255) / 256), 256>>>(ei, Wc2, bc2, (float2*)d_out, E);
}

// round 13
// speedup vs baseline: 1.3072x; 1.1906x over previous
#include <cuda_runtime.h>
#include <cuda_fp16.h>

#define NN 100000
#define EE 1600000
#define IC 128
#define HH 64

// ---------------- device scratch (no allocs allowed) ----------------
// g_deg starts zero (static init) and scan1 re-zeroes it after reading,
// so "deg == 0 on entry" holds for every kernel_launch call / graph replay.
__device__ __align__(16) int    g_deg[NN];
__device__ __align__(16) float  g_dis[NN];
__device__ __align__(16) int    g_ptmp[NN];
__device__ __align__(16) int    g_bsum[512];
__device__ __align__(16) int    g_boff[512];
__device__ __align__(16) int    g_rowptr[NN + 1];
__device__ __align__(16) int    g_cursor[NN];
__device__ __align__(16) int2   g_csre[EE];      // {src, norm (fp32 bits)}
__device__ __align__(16) __half g_h0h[NN * HH];  // x @ W1 (fp16)
__device__ __align__(16) __half g_t1h[NN * HH];  // relu(agg1 + b1) (fp16)
__device__ __align__(16) float  g_at[NN * HH];   // agg2 of t1 (fp32, pre-W2)
__device__ __align__(16) __half g_ph[NN * HH];   // p (fp16, bias folded)
__device__ __align__(16) __half g_qh[NN * HH];   // q (fp16, bias folded)
__device__ __align__(16) float  g_Wpq[2 * HH * HH]; // [Wp | Wq] = W2 @ [Wc1_top | Wc1_bot]
__device__ __align__(16) float  g_bp[HH];
__device__ __align__(16) float  g_bq[HH];

// ---------------- GEMM1: h0 = x @ W1 -> fp16 ; fused dst-degree histogram ----------------
__global__ __launch_bounds__(256) void k_gemm1(const float* __restrict__ x,
                                               const float* __restrict__ W1,
                                               const int* __restrict__ ei,
                                               int n, int E) {
    // fused degree histogram: grid*256 = 800k threads, 2 edges each
    {
        int t = blockIdx.x * 256 + threadIdx.x;
        int stride = gridDim.x * 256;
        for (int e = t; e < E; e += stride)
            atomicAdd(&g_deg[ei[E + e]], 1);
    }
    __shared__ float Ws[IC * HH];
    __shared__ float xs[8][4 * IC];
    int tid = threadIdx.x;
    for (int i = tid; i < IC * HH / 4; i += 256)
        ((float4*)Ws)[i] = ((const float4*)W1)[i];
    __syncthreads();
    int w = tid >> 5, lane = tid & 31;
    int r0 = blockIdx.x * 32 + w * 4;
    if (r0 >= n) return;
    int nr = min(4, n - r0);
    const float4* xsrc = (const float4*)(x + (size_t)r0 * IC);
    float4* xd = (float4*)xs[w];
    for (int i = lane; i < nr * (IC / 4); i += 32) xd[i] = xsrc[i];
    __syncwarp();
    float acc[4][2] = {};
#pragma unroll 8
    for (int k = 0; k < IC; k++) {
        float w0 = Ws[k * HH + lane], w1 = Ws[k * HH + lane + 32];
#pragma unroll
        for (int rr = 0; rr < 4; rr++) {
            float xv = xs[w][rr * IC + k];
            acc[rr][0] = fmaf(xv, w0, acc[rr][0]);
            acc[rr][1] = fmaf(xv, w1, acc[rr][1]);
        }
    }
    for (int rr = 0; rr < nr; rr++) {
        int r = r0 + rr;
        g_h0h[r * HH + lane]      = __float2half(acc[rr][0]);
        g_h0h[r * HH + lane + 32] = __float2half(acc[rr][1]);
    }
}

// ---------------- weight pre-combination: Wpq = W2 @ [Wc1_top | Wc1_bot] ----------------
__global__ __launch_bounds__(256) void k_wcomb(const float* __restrict__ W2,
                                               const float* __restrict__ b2,
                                               const float* __restrict__ Wc1,
                                               const float* __restrict__ bc1) {
    __shared__ float sW2[HH * HH];
    __shared__ float sWc1[2 * HH * HH];
    int tid = threadIdx.x;
    for (int i = tid; i < HH * HH / 4; i += 256)
        ((float4*)sW2)[i] = ((const float4*)W2)[i];
    for (int i = tid; i < 2 * HH * HH / 4; i += 256)
        ((float4*)sWc1)[i] = ((const float4*)Wc1)[i];
    __syncthreads();
    int kbase = blockIdx.x * 8;
    for (int idx = tid; idx < 8 * HH; idx += 256) {
        int k = kbase + (idx >> 6), c = idx & 63;
        float sp = 0.f, sq = 0.f;
#pragma unroll 8
        for (int j = 0; j < HH; j++) {
            float w = sW2[k * HH + j];
            sp = fmaf(w, sWc1[j * HH + c], sp);
            sq = fmaf(w, sWc1[(HH + j) * HH + c], sq);
        }
        g_Wpq[k * HH + c]           = sp;
        g_Wpq[HH * HH + k * HH + c] = sq;
    }
    if (blockIdx.x == 0 && tid < HH) {
        float sp = bc1[tid], sq = 0.f;
        for (int j = 0; j < HH; j++) {
            float b = b2[j];
            sp = fmaf(b, sWc1[j * HH + tid], sp);
            sq = fmaf(b, sWc1[(HH + j) * HH + tid], sq);
        }
        g_bp[tid] = sp;
        g_bq[tid] = sq;
    }
}

// ---------------- scan1: reads deg, resets it to 0, computes dis ----------------
__global__ void k_scan1(int n) {
    __shared__ int sh[256];
    int i = blockIdx.x * 256 + threadIdx.x;
    int v = (i < n) ? g_deg[i] : 0;
    if (i < n) {
        g_dis[i] = rsqrtf((float)(v + 1));
        g_deg[i] = 0;                       // reset for next replay
    }
    sh[threadIdx.x] = v;
    __syncthreads();
    int acc = v;
#pragma unroll
    for (int o = 1; o < 256; o <<= 1) {
        int t = (threadIdx.x >= o) ? sh[threadIdx.x - o] : 0;
        __syncthreads();
        acc += t; sh[threadIdx.x] = acc;
        __syncthreads();
    }
    if (i < n) g_ptmp[i] = acc - v;
    if (threadIdx.x == 255) g_bsum[blockIdx.x] = acc;
}

__global__ void k_scan2(int nb) {
    __shared__ int sh[512];
    int t = threadIdx.x;
    int v = (t < nb) ? g_bsum[t] : 0;
    sh[t] = v;
    __syncthreads();
    int acc = v;
#pragma unroll
    for (int o = 1; o < 512; o <<= 1) {
        int x = (t >= o) ? sh[t - o] : 0;
        __syncthreads();
        acc += x; sh[t] = acc;
        __syncthreads();
    }
    if (t < nb) g_boff[t] = acc - v;
}

__global__ void k_scan3(int n, int E) {
    int i = blockIdx.x * 256 + threadIdx.x;
    if (i < n) {
        int r = g_ptmp[i] + g_boff[blockIdx.x];
        g_rowptr[i] = r;
        g_cursor[i] = r;
    }
    if (i == 0) g_rowptr[n] = E;
}

// ---------------- CSR fill: one STG.64 per edge ----------------
__global__ void k_fill(const int* __restrict__ ei, int E) {
    int e = blockIdx.x * 256 + threadIdx.x;
    if (e >= E) return;
    int s = ei[e];
    int d = ei[E + e];
    int pos = atomicAdd(&g_cursor[d], 1);
    int2 v;
    v.x = s;
    v.y = __float_as_int(g_dis[s] * g_dis[d]);
    g_csre[pos] = v;
}

// ---------------- CSR gather on fp16 rows (half2 lanes, 4-edge unroll) ----------------
template<int LAYER>
__global__ __launch_bounds__(256) void k_gather(const float* __restrict__ bias, int n) {
    int w = threadIdx.x >> 5, lane = threadIdx.x & 31;
    int node = blockIdx.x * 8 + w;
    if (node >= n) return;
    const __half2* h = (const __half2*)(LAYER ? g_t1h : g_h0h);
    float dd = g_dis[node];
    float d2 = dd * dd;
    float2 self = __half22float2(h[node * 32 + lane]);
    float ax = self.x * d2, ay = self.y * d2;
    int i = g_rowptr[node], end = g_rowptr[node + 1];
    for (; i + 4 <= end; i += 4) {
        int2 e0 = g_csre[i],     e1 = g_csre[i + 1];
        int2 e2 = g_csre[i + 2], e3 = g_csre[i + 3];
        float n0 = __int_as_float(e0.y), n1 = __int_as_float(e1.y);
        float n2 = __int_as_float(e2.y), n3 = __int_as_float(e3.y);
        float2 v0 = __half22float2(h[e0.x * 32 + lane]);
        float2 v1 = __half22float2(h[e1.x * 32 + lane]);
        float2 v2 = __half22float2(h[e2.x * 32 + lane]);
        float2 v3 = __half22float2(h[e3.x * 32 + lane]);
        ax = fmaf(v0.x, n0, ax); ay = fmaf(v0.y, n0, ay);
        ax = fmaf(v1.x, n1, ax); ay = fmaf(v1.y, n1, ay);
        ax = fmaf(v2.x, n2, ax); ay = fmaf(v2.y, n2, ay);
        ax = fmaf(v3.x, n3, ax); ay = fmaf(v3.y, n3, ay);
    }
    for (; i < end; i++) {
        int2 e0 = g_csre[i];
        float n0 = __int_as_float(e0.y);
        float2 v0 = __half22float2(h[e0.x * 32 + lane]);
        ax = fmaf(v0.x, n0, ax); ay = fmaf(v0.y, n0, ay);
    }
    if (LAYER == 0) {
        float2 bb = __ldg((const float2*)bias + lane);
        float rx = fmaxf(ax + bb.x, 0.f);
        float ry = fmaxf(ay + bb.y, 0.f);
        ((__half2*)g_t1h)[node * 32 + lane] = __floats2half2_rn(rx, ry);
    } else {
        float2 r; r.x = ax; r.y = ay;
        ((float2*)g_at)[node * 32 + lane] = r;
    }
}

// ---------------- p/q projection from aggt with pre-combined weights ----------------
__global__ __launch_bounds__(256) void k_pqc(int n) {
    __shared__ float Ws[2 * HH * HH];
    __shared__ float hs[8][4 * HH];
    int tid = threadIdx.x;
    for (int i = tid; i < 2 * HH * HH / 4; i += 256)
        ((float4*)Ws)[i] = ((const float4*)g_Wpq)[i];
    __syncthreads();
    int w = tid >> 5, lane = tid & 31;
    int r0 = blockIdx.x * 32 + w * 4;
    if (r0 >= n) return;
    int nr = min(4, n - r0);
    const float4* hsrc = (const float4*)(g_at + (size_t)r0 * HH);
    float4* hd = (float4*)hs[w];
    for (int i = lane; i < nr * (HH / 4); i += 32) hd[i] = hsrc[i];
    __syncwarp();
    float ap[4][2] = {}, aq[4][2] = {};
#pragma unroll 4
    for (int k = 0; k < HH; k++) {
        float wp0 = Ws[k * HH + lane],        wp1 = Ws[k * HH + lane + 32];
        float wq0 = Ws[(HH + k) * HH + lane], wq1 = Ws[(HH + k) * HH + lane + 32];
#pragma unroll
        for (int rr = 0; rr < 4; rr++) {
            float hv = hs[w][rr * HH + k];
            ap[rr][0] = fmaf(hv, wp0, ap[rr][0]);
            ap[rr][1] = fmaf(hv, wp1, ap[rr][1]);
            aq[rr][0] = fmaf(hv, wq0, aq[rr][0]);
            aq[rr][1] = fmaf(hv, wq1, aq[rr][1]);
        }
    }
    float p0 = g_bp[lane], p1 = g_bp[lane + 32];
    float q0 = g_bq[lane], q1 = g_bq[lane + 32];
    for (int rr = 0; rr < nr; rr++) {
        int r = r0 + rr;
        g_ph[r * HH + lane]      = __float2half(ap[rr][0] + p0);
        g_ph[r * HH + lane + 32] = __float2half(ap[rr][1] + p1);
        g_qh[r * HH + lane]      = __float2half(aq[rr][0] + q0);
        g_qh[r * HH + lane + 32] = __float2half(aq[rr][1] + q1);
    }
}

// ---------------- edge classifier: 8 lanes x 2 edges, 4 LDG.128 in flight ----------------
__global__ __launch_bounds__(256) void k_cls(const int* __restrict__ ei,
                                             const float* __restrict__ Wc2,
                                             const float* __restrict__ bc2,
                                             float2* __restrict__ out, int E) {
    int t = blockIdx.x * 256 + threadIdx.x;
    int e0 = (t >> 3) * 2;          // E is even; e0, e0+1 both valid when e0 < E
    if (e0 >= E) return;
    int l = t & 7;
    int2 ss = *(const int2*)(ei + e0);        // src of both edges
    int2 dd = *(const int2*)(ei + E + e0);    // dst of both edges
    uint4 pv0 = *(const uint4*)(g_ph + (size_t)ss.x * HH + l * 8);
    uint4 qv0 = *(const uint4*)(g_qh + (size_t)dd.x * HH + l * 8);
    uint4 pv1 = *(const uint4*)(g_ph + (size_t)ss.y * HH + l * 8);
    uint4 qv1 = *(const uint4*)(g_qh + (size_t)dd.y * HH + l * 8);
    const __half2* pp0 = (const __half2*)&pv0;
    const __half2* qq0 = (const __half2*)&qv0;
    const __half2* pp1 = (const __half2*)&pv1;
    const __half2* qq1 = (const __half2*)&qv1;
    float a0 = 0.f, a1 = 0.f, b0 = 0.f, b1 = 0.f;
#pragma unroll
    for (int j = 0; j < 4; j++) {
        int c = l * 8 + j * 2;
        float2 wA = __ldg((const float2*)Wc2 + c);
        float2 wB = __ldg((const float2*)Wc2 + c + 1);
        float2 pa = __half22float2(pp0[j]);
        float2 qa = __half22float2(qq0[j]);
        float u0 = fmaxf(pa.x + qa.x, 0.f);
        float u1 = fmaxf(pa.y + qa.y, 0.f);
        a0 += u0 * wA.x + u1 * wB.x;
        a1 += u0 * wA.y + u1 * wB.y;
        float2 pb = __half22float2(pp1[j]);
        float2 qb = __half22float2(qq1[j]);
        float v0 = fmaxf(pb.x + qb.x, 0.f);
        float v1 = fmaxf(pb.y + qb.y, 0.f);
        b0 += v0 * wA.x + v1 * wB.x;
        b1 += v0 * wA.y + v1 * wB.y;
    }
#pragma unroll
    for (int o = 4; o > 0; o >>= 1) {
        a0 += __shfl_down_sync(0xffffffffu, a0, o, 8);
        a1 += __shfl_down_sync(0xffffffffu, a1, o, 8);
        b0 += __shfl_down_sync(0xffffffffu, b0, o, 8);
        b1 += __shfl_down_sync(0xffffffffu, b1, o, 8);
    }
    if (l == 0) {
        float c0 = __ldg(&bc2[0]), c1 = __ldg(&bc2[1]);
        float4 r;
        r.x = a0 + c0; r.y = a1 + c1;
        r.z = b0 + c0; r.w = b1 + c1;
        *(float4*)(out + e0) = r;
    }
}

// ---------------- launch ----------------
extern "C" void kernel_launch(void* const* d_in, const int* in_sizes, int n_in,
                              void* d_out, int out_size) {
    const float* x   = (const float*)d_in[0];
    const int*   ei  = (const int*)d_in[1];   // int32 edge_index (verified R4+)
    const float* W1  = (const float*)d_in[2];
    const float* b1  = (const float*)d_in[3];
    const float* W2  = (const float*)d_in[4];
    const float* b2  = (const float*)d_in[5];
    const float* Wc1 = (const float*)d_in[6];
    const float* bc1 = (const float*)d_in[7];
    const float* Wc2 = (const float*)d_in[8];
    const float* bc2 = (const float*)d_in[9];

    int N = in_sizes[0] / IC;   // 100000
    int E = in_sizes[1] / 2;    // 1600000
    int nb = (N + 255) / 256;

    k_gemm1<<<(N + 31) / 32, 256>>>(x, W1, ei, N, E);   // + degree histogram
    k_wcomb<<<8, 256>>>(W2, b2, Wc1, bc1);
    k_scan1<<<nb, 256>>>(N);                            // reads + resets deg
    k_scan2<<<1, 512>>>(nb);
    k_scan3<<<nb, 256>>>(N, E);
    k_fill<<<(E + 255) / 256, 256>>>(ei, E);

    k_gather<0><<<(N + 7) / 8, 256>>>(b1, N);
    k_gather<1><<<(N + 7) / 8, 256>>>(nullptr, N);
    k_pqc<<<(N + 31) / 32, 256>>>(N);
    k_cls<<<(int)(((long long)E * 4 + 255) / 256), 256>>>(ei, Wc2, bc2, (float2*)d_out, E);
}

// round 14
// speedup vs baseline: 1.3723x; 1.0498x over previous
#include <cuda_runtime.h>
#include <cuda_fp16.h>

#define NN 100000
#define EE 1600000
#define IC 128
#define HH 64

// ---------------- device scratch (no allocs allowed) ----------------
// g_deg starts zero (static init) and scan1 re-zeroes it after reading,
// so "deg == 0 on entry" holds for every kernel_launch call / graph replay.
__device__ __align__(16) int    g_deg[NN];
__device__ __align__(16) float  g_dis[NN];
__device__ __align__(16) int    g_ptmp[NN];
__device__ __align__(16) int    g_bsum[512];
__device__ __align__(16) int    g_boff[512];
__device__ __align__(16) int    g_rowptr[NN + 1];
__device__ __align__(16) int    g_cursor[NN];
__device__ __align__(16) int2   g_csre[EE];      // {src, norm (fp32 bits)}
__device__ __align__(16) __half g_h0h[NN * HH];  // x @ W1 (fp16)
__device__ __align__(16) __half g_t1h[NN * HH];  // relu(agg1 + b1) (fp16)
__device__ __align__(16) float  g_at[NN * HH];   // agg2 of t1 (fp32, pre-W2)
__device__ __align__(16) __half g_ph[NN * HH];   // p (fp16, bias folded)
__device__ __align__(16) __half g_qh[NN * HH];   // q (fp16, bias folded)
__device__ __align__(16) float  g_Wpq[2 * HH * HH]; // [Wp | Wq] = W2 @ [Wc1_top | Wc1_bot]
__device__ __align__(16) float  g_bp[HH];
__device__ __align__(16) float  g_bq[HH];

// ---------------- GEMM1: h0 = x @ W1 -> fp16 ; 128 rows/block ; fused histogram ----------------
__global__ __launch_bounds__(256) void k_gemm1(const float* __restrict__ x,
                                               const float* __restrict__ W1,
                                               const int* __restrict__ ei,
                                               int n, int E) {
    // fused degree histogram
    {
        int t = blockIdx.x * 256 + threadIdx.x;
        int stride = gridDim.x * 256;
        for (int e = t; e < E; e += stride)
            atomicAdd(&g_deg[ei[E + e]], 1);
    }
    __shared__ float Ws[IC * HH];       // 32 KB, loaded once per block
    __shared__ float xs[8][4 * IC];     // 16 KB
    int tid = threadIdx.x;
    for (int i = tid; i < IC * HH / 4; i += 256)
        ((float4*)Ws)[i] = ((const float4*)W1)[i];
    __syncthreads();
    int w = tid >> 5, lane = tid & 31;
#pragma unroll 1
    for (int g = 0; g < 4; g++) {
        int r0 = blockIdx.x * 128 + w * 16 + g * 4;
        if (r0 >= n) continue;
        int nr = min(4, n - r0);
        const float4* xsrc = (const float4*)(x + (size_t)r0 * IC);
        float4* xd = (float4*)xs[w];
        for (int i = lane; i < nr * (IC / 4); i += 32) xd[i] = xsrc[i];
        __syncwarp();
        float acc[4][2] = {};
#pragma unroll 8
        for (int k = 0; k < IC; k++) {
            float w0 = Ws[k * HH + lane], w1 = Ws[k * HH + lane + 32];
#pragma unroll
            for (int rr = 0; rr < 4; rr++) {
                float xv = xs[w][rr * IC + k];
                acc[rr][0] = fmaf(xv, w0, acc[rr][0]);
                acc[rr][1] = fmaf(xv, w1, acc[rr][1]);
            }
        }
        for (int rr = 0; rr < nr; rr++) {
            int r = r0 + rr;
            g_h0h[r * HH + lane]      = __float2half(acc[rr][0]);
            g_h0h[r * HH + lane + 32] = __float2half(acc[rr][1]);
        }
        __syncwarp();
    }
}

// ---------------- scan1: reads deg, resets it to 0, computes dis ----------------
__global__ void k_scan1(int n) {
    __shared__ int sh[256];
    int i = blockIdx.x * 256 + threadIdx.x;
    int v = (i < n) ? g_deg[i] : 0;
    if (i < n) {
        g_dis[i] = rsqrtf((float)(v + 1));
        g_deg[i] = 0;                       // reset for next replay
    }
    sh[threadIdx.x] = v;
    __syncthreads();
    int acc = v;
#pragma unroll
    for (int o = 1; o < 256; o <<= 1) {
        int t = (threadIdx.x >= o) ? sh[threadIdx.x - o] : 0;
        __syncthreads();
        acc += t; sh[threadIdx.x] = acc;
        __syncthreads();
    }
    if (i < n) g_ptmp[i] = acc - v;
    if (threadIdx.x == 255) g_bsum[blockIdx.x] = acc;
}

// ---------------- scan2 (block 0) + wcomb (blocks 1..8) ----------------
__global__ __launch_bounds__(512) void k_scan2_wcomb(int nb,
                                                     const float* __restrict__ W2,
                                                     const float* __restrict__ b2,
                                                     const float* __restrict__ Wc1,
                                                     const float* __restrict__ bc1) {
    __shared__ float smem[12 * 1024];   // 48 KB: scan uses first 2KB as int; wcomb tiles
    int tid = threadIdx.x;
    if (blockIdx.x == 0) {
        int* sh = (int*)smem;
        int v = (tid < nb) ? g_bsum[tid] : 0;
        sh[tid] = v;
        __syncthreads();
        int acc = v;
#pragma unroll
        for (int o = 1; o < 512; o <<= 1) {
            int x = (tid >= o) ? sh[tid - o] : 0;
            __syncthreads();
            acc += x; sh[tid] = acc;
            __syncthreads();
        }
        if (tid < nb) g_boff[tid] = acc - v;
    } else {
        float* sW2  = smem;              // 16 KB
        float* sWc1 = smem + HH * HH;    // 32 KB
        for (int i = tid; i < HH * HH / 4; i += 512)
            ((float4*)sW2)[i] = ((const float4*)W2)[i];
        for (int i = tid; i < 2 * HH * HH / 4; i += 512)
            ((float4*)sWc1)[i] = ((const float4*)Wc1)[i];
        __syncthreads();
        int kbase = (blockIdx.x - 1) * 8;
        for (int idx = tid; idx < 8 * HH; idx += 512) {
            int k = kbase + (idx >> 6), c = idx & 63;
            float sp = 0.f, sq = 0.f;
#pragma unroll 8
            for (int j = 0; j < HH; j++) {
                float w = sW2[k * HH + j];
                sp = fmaf(w, sWc1[j * HH + c], sp);
                sq = fmaf(w, sWc1[(HH + j) * HH + c], sq);
            }
            g_Wpq[k * HH + c]           = sp;
            g_Wpq[HH * HH + k * HH + c] = sq;
        }
        if (blockIdx.x == 1 && tid < HH) {
            float sp = bc1[tid], sq = 0.f;
            for (int j = 0; j < HH; j++) {
                float b = b2[j];
                sp = fmaf(b, sWc1[j * HH + tid], sp);
                sq = fmaf(b, sWc1[(HH + j) * HH + tid], sq);
            }
            g_bp[tid] = sp;
            g_bq[tid] = sq;
        }
    }
}

__global__ void k_scan3(int n, int E) {
    int i = blockIdx.x * 256 + threadIdx.x;
    if (i < n) {
        int r = g_ptmp[i] + g_boff[blockIdx.x];
        g_rowptr[i] = r;
        g_cursor[i] = r;
    }
    if (i == 0) g_rowptr[n] = E;
}

// ---------------- CSR fill: one STG.64 per edge ----------------
__global__ void k_fill(const int* __restrict__ ei, int E) {
    int e = blockIdx.x * 256 + threadIdx.x;
    if (e >= E) return;
    int s = ei[e];
    int d = ei[E + e];
    int pos = atomicAdd(&g_cursor[d], 1);
    int2 v;
    v.x = s;
    v.y = __float_as_int(g_dis[s] * g_dis[d]);
    g_csre[pos] = v;
}

// ---------------- CSR gather on fp16 rows (half2 lanes, 4-edge unroll) ----------------
template<int LAYER>
__global__ __launch_bounds__(256) void k_gather(const float* __restrict__ bias, int n) {
    int w = threadIdx.x >> 5, lane = threadIdx.x & 31;
    int node = blockIdx.x * 8 + w;
    if (node >= n) return;
    const __half2* h = (const __half2*)(LAYER ? g_t1h : g_h0h);
    float dd = g_dis[node];
    float d2 = dd * dd;
    float2 self = __half22float2(h[node * 32 + lane]);
    float ax = self.x * d2, ay = self.y * d2;
    int i = g_rowptr[node], end = g_rowptr[node + 1];
    for (; i + 4 <= end; i += 4) {
        int2 e0 = g_csre[i],     e1 = g_csre[i + 1];
        int2 e2 = g_csre[i + 2], e3 = g_csre[i + 3];
        float n0 = __int_as_float(e0.y), n1 = __int_as_float(e1.y);
        float n2 = __int_as_float(e2.y), n3 = __int_as_float(e3.y);
        float2 v0 = __half22float2(h[e0.x * 32 + lane]);
        float2 v1 = __half22float2(h[e1.x * 32 + lane]);
        float2 v2 = __half22float2(h[e2.x * 32 + lane]);
        float2 v3 = __half22float2(h[e3.x * 32 + lane]);
        ax = fmaf(v0.x, n0, ax); ay = fmaf(v0.y, n0, ay);
        ax = fmaf(v1.x, n1, ax); ay = fmaf(v1.y, n1, ay);
        ax = fmaf(v2.x, n2, ax); ay = fmaf(v2.y, n2, ay);
        ax = fmaf(v3.x, n3, ax); ay = fmaf(v3.y, n3, ay);
    }
    for (; i < end; i++) {
        int2 e0 = g_csre[i];
        float n0 = __int_as_float(e0.y);
        float2 v0 = __half22float2(h[e0.x * 32 + lane]);
        ax = fmaf(v0.x, n0, ax); ay = fmaf(v0.y, n0, ay);
    }
    if (LAYER == 0) {
        float2 bb = __ldg((const float2*)bias + lane);
        float rx = fmaxf(ax + bb.x, 0.f);
        float ry = fmaxf(ay + bb.y, 0.f);
        ((__half2*)g_t1h)[node * 32 + lane] = __floats2half2_rn(rx, ry);
    } else {
        float2 r; r.x = ax; r.y = ay;
        ((float2*)g_at)[node * 32 + lane] = r;
    }
}

// ---------------- p/q projection: 128 rows/block, Wpq loaded once ----------------
__global__ __launch_bounds__(256) void k_pqc(int n) {
    __shared__ float Ws[2 * HH * HH];   // 32 KB
    __shared__ float hs[8][4 * HH];     // 8 KB
    int tid = threadIdx.x;
    for (int i = tid; i < 2 * HH * HH / 4; i += 256)
        ((float4*)Ws)[i] = ((const float4*)g_Wpq)[i];
    __syncthreads();
    int w = tid >> 5, lane = tid & 31;
    float p0 = g_bp[lane], p1 = g_bp[lane + 32];
    float q0 = g_bq[lane], q1 = g_bq[lane + 32];
#pragma unroll 1
    for (int g = 0; g < 4; g++) {
        int r0 = blockIdx.x * 128 + w * 16 + g * 4;
        if (r0 >= n) continue;
        int nr = min(4, n - r0);
        const float4* hsrc = (const float4*)(g_at + (size_t)r0 * HH);
        float4* hd = (float4*)hs[w];
        for (int i = lane; i < nr * (HH / 4); i += 32) hd[i] = hsrc[i];
        __syncwarp();
        float ap[4][2] = {}, aq[4][2] = {};
#pragma unroll 4
        for (int k = 0; k < HH; k++) {
            float wp0 = Ws[k * HH + lane],        wp1 = Ws[k * HH + lane + 32];
            float wq0 = Ws[(HH + k) * HH + lane], wq1 = Ws[(HH + k) * HH + lane + 32];
#pragma unroll
            for (int rr = 0; rr < 4; rr++) {
                float hv = hs[w][rr * HH + k];
                ap[rr][0] = fmaf(hv, wp0, ap[rr][0]);
                ap[rr][1] = fmaf(hv, wp1, ap[rr][1]);
                aq[rr][0] = fmaf(hv, wq0, aq[rr][0]);
                aq[rr][1] = fmaf(hv, wq1, aq[rr][1]);
            }
        }
        for (int rr = 0; rr < nr; rr++) {
            int r = r0 + rr;
            g_ph[r * HH + lane]      = __float2half(ap[rr][0] + p0);
            g_ph[r * HH + lane + 32] = __float2half(ap[rr][1] + p1);
            g_qh[r * HH + lane]      = __float2half(aq[rr][0] + q0);
            g_qh[r * HH + lane + 32] = __float2half(aq[rr][1] + q1);
        }
        __syncwarp();
    }
}

// ---------------- edge classifier: 8 lanes x 4 edges, 8 LDG.128 in flight ----------------
__global__ __launch_bounds__(256) void k_cls(const int* __restrict__ ei,
                                             const float* __restrict__ Wc2,
                                             const float* __restrict__ bc2,
                                             float2* __restrict__ out, int E) {
    int t = blockIdx.x * 256 + threadIdx.x;
    int e0 = (t >> 3) * 4;          // E divisible by 4
    if (e0 >= E) return;
    int l = t & 7;
    int4 ss = *(const int4*)(ei + e0);
    int4 dd = *(const int4*)(ei + E + e0);
    uint4 pv0 = *(const uint4*)(g_ph + (size_t)ss.x * HH + l * 8);
    uint4 qv0 = *(const uint4*)(g_qh + (size_t)dd.x * HH + l * 8);
    uint4 pv1 = *(const uint4*)(g_ph + (size_t)ss.y * HH + l * 8);
    uint4 qv1 = *(const uint4*)(g_qh + (size_t)dd.y * HH + l * 8);
    uint4 pv2 = *(const uint4*)(g_ph + (size_t)ss.z * HH + l * 8);
    uint4 qv2 = *(const uint4*)(g_qh + (size_t)dd.z * HH + l * 8);
    uint4 pv3 = *(const uint4*)(g_ph + (size_t)ss.w * HH + l * 8);
    uint4 qv3 = *(const uint4*)(g_qh + (size_t)dd.w * HH + l * 8);
    const __half2* pp0 = (const __half2*)&pv0;
    const __half2* qq0 = (const __half2*)&qv0;
    const __half2* pp1 = (const __half2*)&pv1;
    const __half2* qq1 = (const __half2*)&qv1;
    const __half2* pp2 = (const __half2*)&pv2;
    const __half2* qq2 = (const __half2*)&qv2;
    const __half2* pp3 = (const __half2*)&pv3;
    const __half2* qq3 = (const __half2*)&qv3;
    float a0 = 0.f, a1 = 0.f, b0 = 0.f, b1 = 0.f;
    float c0 = 0.f, c1 = 0.f, d0 = 0.f, d1 = 0.f;
#pragma unroll
    for (int j = 0; j < 4; j++) {
        int c = l * 8 + j * 2;
        float2 wA = __ldg((const float2*)Wc2 + c);
        float2 wB = __ldg((const float2*)Wc2 + c + 1);
        {
            float2 pa = __half22float2(pp0[j]);
            float2 qa = __half22float2(qq0[j]);
            float u0 = fmaxf(pa.x + qa.x, 0.f);
            float u1 = fmaxf(pa.y + qa.y, 0.f);
            a0 += u0 * wA.x + u1 * wB.x;
            a1 += u0 * wA.y + u1 * wB.y;
        }
        {
            float2 pa = __half22float2(pp1[j]);
            float2 qa = __half22float2(qq1[j]);
            float u0 = fmaxf(pa.x + qa.x, 0.f);
            float u1 = fmaxf(pa.y + qa.y, 0.f);
            b0 += u0 * wA.x + u1 * wB.x;
            b1 += u0 * wA.y + u1 * wB.y;
        }
        {
            float2 pa = __half22float2(pp2[j]);
            float2 qa = __half22float2(qq2[j]);
            float u0 = fmaxf(pa.x + qa.x, 0.f);
            float u1 = fmaxf(pa.y + qa.y, 0.f);
            c0 += u0 * wA.x + u1 * wB.x;
            c1 += u0 * wA.y + u1 * wB.y;
        }
        {
            float2 pa = __half22float2(pp3[j]);
            float2 qa = __half22float2(qq3[j]);
            float u0 = fmaxf(pa.x + qa.x, 0.f);
            float u1 = fmaxf(pa.y + qa.y, 0.f);
            d0 += u0 * wA.x + u1 * wB.x;
            d1 += u0 * wA.y + u1 * wB.y;
        }
    }
#pragma unroll
    for (int o = 4; o > 0; o >>= 1) {
        a0 += __shfl_down_sync(0xffffffffu, a0, o, 8);
        a1 += __shfl_down_sync(0xffffffffu, a1, o, 8);
        b0 += __shfl_down_sync(0xffffffffu, b0, o, 8);
        b1 += __shfl_down_sync(0xffffffffu, b1, o, 8);
        c0 += __shfl_down_sync(0xffffffffu, c0, o, 8);
        c1 += __shfl_down_sync(0xffffffffu, c1, o, 8);
        d0 += __shfl_down_sync(0xffffffffu, d0, o, 8);
        d1 += __shfl_down_sync(0xffffffffu, d1, o, 8);
    }
    if (l == 0) {
        float z0 = __ldg(&bc2[0]), z1 = __ldg(&bc2[1]);
        float4 r0, r1;
        r0.x = a0 + z0; r0.y = a1 + z1;
        r0.z = b0 + z0; r0.w = b1 + z1;
        r1.x = c0 + z0; r1.y = c1 + z1;
        r1.z = d0 + z0; r1.w = d1 + z1;
        *(float4*)(out + e0)     = r0;
        *(float4*)(out + e0 + 2) = r1;
    }
}

// ---------------- launch ----------------
extern "C" void kernel_launch(void* const* d_in, const int* in_sizes, int n_in,
                              void* d_out, int out_size) {
    const float* x   = (const float*)d_in[0];
    const int*   ei  = (const int*)d_in[1];   // int32 edge_index (verified R4+)
    const float* W1  = (const float*)d_in[2];
    const float* b1  = (const float*)d_in[3];
    const float* W2  = (const float*)d_in[4];
    const float* b2  = (const float*)d_in[5];
    const float* Wc1 = (const float*)d_in[6];
    const float* bc1 = (const float*)d_in[7];
    const float* Wc2 = (const float*)d_in[8];
    const float* bc2 = (const float*)d_in[9];

    int N = in_sizes[0] / IC;   // 100000
    int E = in_sizes[1] / 2;    // 1600000
    int nb = (N + 255) / 256;

    k_gemm1<<<(N + 127) / 128, 256>>>(x, W1, ei, N, E);  // + degree histogram
    k_scan1<<<nb, 256>>>(N);                             // reads + resets deg
    k_scan2_wcomb<<<9, 512>>>(nb, W2, b2, Wc1, bc1);     // scan2 + weight combine
    k_scan3<<<nb, 256>>>(N, E);
    k_fill<<<(E + 255) / 256, 256>>>(ei, E);

    k_gather<0><<<(N + 7) / 8, 256>>>(b1, N);
    k_gather<1><<<(N + 7) / 8, 256>>>(nullptr, N);
    k_pqc<<<(N + 127) / 128, 256>>>(N);
    k_cls<<<(int)(((long long)E * 2 + 255) / 256), 256>>>(ei, Wc2, bc2, (float2*)d_out, E);
}